// round 5
// baseline (speedup 1.0000x reference)
#include <cuda_runtime.h>
#include <math.h>
#include <stdint.h>

#define BB  256
#define TT  168
#define INF 64
#define HH  512
#define HOR 24
#define NBLK 128

// ---- device scratch (no allocations allowed) ----
__device__ float g_h[2][2][BB * HH];   // [layer][pingpong][B*H]
__device__ float g_xin[BB];            // decoder scalar feedback
__device__ volatile unsigned g_bar_gen;
__device__ unsigned g_bar_count;

__device__ __forceinline__ float sigmoidf_(float x) { return 1.0f / (1.0f + expf(-x)); }

__global__ void init_state_kernel() {
    int i = blockIdx.x * blockDim.x + threadIdx.x;
    if (i < BB * HH) {
        g_h[0][0][i] = 0.0f;
        g_h[1][0][i] = 0.0f;
    }
    if (i < BB) g_xin[i] = 0.0f;
    if (i == 0) { g_bar_gen = 0; g_bar_count = 0; }
}

// ---------------------------------------------------------------------------
// Software grid barrier (all NBLK blocks resident). Release = threadfence at
// entry (publishes this block's STGs); acquire = threadfence after spin.
// ---------------------------------------------------------------------------
__device__ __forceinline__ void grid_barrier(unsigned& bar_target) {
    bar_target++;
    __threadfence();
    __syncthreads();
    if (threadIdx.x == 0) {
        unsigned t = atomicAdd(&g_bar_count, 1);
        if (t == NBLK - 1) {
            g_bar_count = 0;
            __threadfence();
            g_bar_gen = bar_target;
        } else {
            while (g_bar_gen < bar_target) { }
            __threadfence();
        }
    }
    __syncthreads();
}

// ---------------------------------------------------------------------------
// GEMM tile machinery (unchanged from R3: cp.async double-buffered,
// BM=32 x 32 hidden cols x 4 gates, 512 threads, 2 rows x 1 col micro-tile)
// ---------------------------------------------------------------------------
#define ROWPAD 36
#define A_WORDS (32 * ROWPAD)
#define W_WORDS (128 * ROWPAD)
#define BUF_WORDS (A_WORDS + W_WORDS)

__device__ __forceinline__ void cpasync16(uint32_t s, const void* g) {
    asm volatile("cp.async.cg.shared.global [%0], [%1], 16;\n" :: "r"(s), "l"(g));
}
__device__ __forceinline__ void cpasync_commit() {
    asm volatile("cp.async.commit_group;\n");
}
__device__ __forceinline__ void cpasync_wait0() {
    asm volatile("cp.async.wait_group 0;\n");
}

__device__ __forceinline__ void load_tile(
    uint32_t sbase,
    const float* __restrict__ Ap, int astr, int aoff,
    const float* __restrict__ Wp, int wstr, int woff,
    int bm, int bn, int tid)
{
#pragma unroll
    for (int it = 0; it < 3; it++) {
        if (it == 2 && tid >= 256) break;
        int c = tid + it * 512;
        if (c < 1024) {
            int r  = c >> 3;        // 0..127 : g*32 + n
            int k4 = c & 7;
            int g  = r >> 5;
            int n  = r & 31;
            const float* gp = Wp + (size_t)(g * HH + bn * 32 + n) * wstr + woff + k4 * 4;
            cpasync16(sbase + (uint32_t)(A_WORDS + r * ROWPAD + k4 * 4) * 4u, gp);
        } else {
            int c2 = c - 1024;
            int m  = c2 >> 3;
            int k4 = c2 & 7;
            const float* gp = Ap + (size_t)(bm * 32 + m) * astr + aoff + k4 * 4;
            cpasync16(sbase + (uint32_t)(m * ROWPAD + k4 * 4) * 4u, gp);
        }
    }
}

// One fused LSTM layer step. c-state lives in caller registers (cr0, cr1).
__device__ __forceinline__ void lstm_layer_step(
    const float* __restrict__ Xin, int Kx, int xstride,
    const float* __restrict__ Wih,
    const float* __restrict__ xin_scalar,
    const float* __restrict__ Wscal,
    const float* __restrict__ Whh,
    const float* __restrict__ bias,
    const float* __restrict__ h_prev,
    float* __restrict__ h_out,
    float& cr0, float& cr1,
    float* smem, uint32_t smem_u32,
    int bn, int bm, int tid, int ty,
    int row0, int col, int idx0, int idx1)
{
    float acc[4][2];
#pragma unroll
    for (int g = 0; g < 4; g++) {
        float b = bias[g * HH + col];
        acc[g][0] = b;
        acc[g][1] = b;
    }

    const int ntiles = (Kx + HH) >> 5;

    auto resolve = [&](int tile, const float*& Ap, int& astr, int& aoff,
                       const float*& Wp, int& wstr, int& woff) {
        int kt = tile * 32;
        if (kt < Kx) {
            Ap = Xin; astr = xstride; aoff = kt;
            Wp = Wih; wstr = Kx;      woff = kt;
        } else {
            Ap = h_prev; astr = HH; aoff = kt - Kx;
            Wp = Whh;    wstr = HH; woff = kt - Kx;
        }
    };

    {
        const float *Ap, *Wp; int astr, aoff, wstr, woff;
        resolve(0, Ap, astr, aoff, Wp, wstr, woff);
        load_tile(smem_u32, Ap, astr, aoff, Wp, wstr, woff, bm, bn, tid);
        cpasync_commit();
    }

#pragma unroll 1
    for (int t = 0; t < ntiles; t++) {
        cpasync_wait0();
        __syncthreads();

        if (t + 1 < ntiles) {
            const float *Ap, *Wp; int astr, aoff, wstr, woff;
            resolve(t + 1, Ap, astr, aoff, Wp, wstr, woff);
            load_tile(smem_u32 + (uint32_t)((t + 1) & 1) * BUF_WORDS * 4u,
                      Ap, astr, aoff, Wp, wstr, woff, bm, bn, tid);
        }
        cpasync_commit();

        const float* sb  = smem + (t & 1) * BUF_WORDS;
        const float* Asb = sb + ty * 2 * ROWPAD;
        const float* Wsb = sb + A_WORDS + (tid & 31) * ROWPAD;

#pragma unroll
        for (int kg = 0; kg < 8; kg++) {
            float4 a0 = *(const float4*)(Asb + kg * 4);
            float4 a1 = *(const float4*)(Asb + ROWPAD + kg * 4);
#pragma unroll
            for (int g = 0; g < 4; g++) {
                float4 w = *(const float4*)(Wsb + g * 32 * ROWPAD + kg * 4);
                acc[g][0] += a0.x * w.x;
                acc[g][0] += a0.y * w.y;
                acc[g][0] += a0.z * w.z;
                acc[g][0] += a0.w * w.w;
                acc[g][1] += a1.x * w.x;
                acc[g][1] += a1.y * w.y;
                acc[g][1] += a1.z * w.z;
                acc[g][1] += a1.w * w.w;
            }
        }
    }

    if (xin_scalar) {
        float x0 = xin_scalar[row0];
        float x1 = xin_scalar[row0 + 1];
#pragma unroll
        for (int g = 0; g < 4; g++) {
            float w = Wscal[g * HH + col];
            acc[g][0] += x0 * w;
            acc[g][1] += x1 * w;
        }
    }

    // PyTorch gate order i,f,g,o
    {
        float ig = sigmoidf_(acc[0][0]);
        float fg = sigmoidf_(acc[1][0]);
        float gg = tanhf(acc[2][0]);
        float og = sigmoidf_(acc[3][0]);
        float c  = fg * cr0 + ig * gg;
        cr0 = c;
        h_out[idx0] = og * tanhf(c);
    }
    {
        float ig = sigmoidf_(acc[0][1]);
        float fg = sigmoidf_(acc[1][1]);
        float gg = tanhf(acc[2][1]);
        float og = sigmoidf_(acc[3][1]);
        float c  = fg * cr1 + ig * gg;
        cr1 = c;
        h_out[idx1] = og * tanhf(c);
    }
}

// ---------------------------------------------------------------------------
// Persistent mega-kernel: entire encoder + decoder + fc.
// grid = (16, 8) = 128 blocks, 512 threads. All blocks resident.
// ---------------------------------------------------------------------------
__global__ __launch_bounds__(512) void lstm_persistent_kernel(
    const float* __restrict__ x,
    const float* __restrict__ eWih0, const float* __restrict__ eWhh0, const float* __restrict__ eb0,
    const float* __restrict__ eWih1, const float* __restrict__ eWhh1, const float* __restrict__ eb1,
    const float* __restrict__ dWih0, const float* __restrict__ dWhh0, const float* __restrict__ db0,
    const float* __restrict__ dWih1, const float* __restrict__ dWhh1, const float* __restrict__ db1,
    const float* __restrict__ fcW,   const float* __restrict__ fcb,
    float* __restrict__ out)
{
    __shared__ __align__(16) float smem[2 * BUF_WORDS];

    const int tid = threadIdx.x;
    const int ty  = tid >> 5;
    const int bn  = blockIdx.x;
    const int bm  = blockIdx.y;
    const int bid = blockIdx.y * 16 + blockIdx.x;
    const int row0 = bm * 32 + ty * 2;
    const int col  = bn * 32 + (tid & 31);
    const int idx0 = row0 * HH + col;
    const int idx1 = idx0 + HH;

    uint32_t smem_u32;
    {
        void* p = (void*)smem;
        asm("{ .reg .u64 t; cvta.to.shared.u64 t, %1; cvt.u32.u64 %0, t; }"
            : "=r"(smem_u32) : "l"(p));
    }

    float* h0[2] = { &g_h[0][0][0], &g_h[0][1][0] };
    float* h1[2] = { &g_h[1][0][0], &g_h[1][1][0] };

    float c0r0 = 0.0f, c0r1 = 0.0f;   // layer-0 cell state (block-private)
    float c1r0 = 0.0f, c1r1 = 0.0f;   // layer-1 cell state

    unsigned bar_t = 0;
    int cur = 0;

    // ---- encoder ----
#pragma unroll 1
    for (int t = 0; t < TT; t++) {
        lstm_layer_step(x + t * INF, INF, TT * INF, eWih0,
                        nullptr, nullptr,
                        eWhh0, eb0, h0[cur], h0[cur ^ 1],
                        c0r0, c0r1, smem, smem_u32, bn, bm, tid, ty,
                        row0, col, idx0, idx1);
        grid_barrier(bar_t);
        lstm_layer_step(h0[cur ^ 1], HH, HH, eWih1,
                        nullptr, nullptr,
                        eWhh1, eb1, h1[cur], h1[cur ^ 1],
                        c1r0, c1r1, smem, smem_u32, bn, bm, tid, ty,
                        row0, col, idx0, idx1);
        grid_barrier(bar_t);
        cur ^= 1;
    }

    // ---- decoder (state carries over from encoder) ----
#pragma unroll 1
    for (int s = 0; s < HOR; s++) {
        lstm_layer_step(nullptr, 0, 0, nullptr,
                        g_xin, dWih0,
                        dWhh0, db0, h0[cur], h0[cur ^ 1],
                        c0r0, c0r1, smem, smem_u32, bn, bm, tid, ty,
                        row0, col, idx0, idx1);
        grid_barrier(bar_t);
        lstm_layer_step(h0[cur ^ 1], HH, HH, dWih1,
                        nullptr, nullptr,
                        dWhh1, db1, h1[cur], h1[cur ^ 1],
                        c1r0, c1r1, smem, smem_u32, bn, bm, tid, ty,
                        row0, col, idx0, idx1);
        grid_barrier(bar_t);

        // fc: blocks 0..7, each handles 32 batch rows (2 rows per warp)
        if (bid < 8) {
            const float* h1o = h1[cur ^ 1];
            int warp = tid >> 5;
            int lane = tid & 31;
#pragma unroll
            for (int r = 0; r < 2; r++) {
                int b = bid * 32 + warp * 2 + r;
                const float* hrow = h1o + b * HH;
                float sum = 0.0f;
#pragma unroll
                for (int k = lane; k < HH; k += 32) sum += hrow[k] * fcW[k];
#pragma unroll
                for (int o = 16; o; o >>= 1) sum += __shfl_xor_sync(0xffffffffu, sum, o);
                if (lane == 0) {
                    float v = sum + fcb[0];
                    out[b * HOR + s] = v;
                    g_xin[b] = v;
                }
            }
        }
        grid_barrier(bar_t);
        cur ^= 1;
    }
}

extern "C" void kernel_launch(void* const* d_in, const int* in_sizes, int n_in,
                              void* d_out, int out_size)
{
    const float* x     = (const float*)d_in[0];
    // d_in[1] = y : unused by the reference
    const float* eWih0 = (const float*)d_in[2];
    const float* eWhh0 = (const float*)d_in[3];
    const float* eb0   = (const float*)d_in[4];
    const float* eWih1 = (const float*)d_in[5];
    const float* eWhh1 = (const float*)d_in[6];
    const float* eb1   = (const float*)d_in[7];
    const float* dWih0 = (const float*)d_in[8];   // [2048,1]
    const float* dWhh0 = (const float*)d_in[9];
    const float* db0   = (const float*)d_in[10];
    const float* dWih1 = (const float*)d_in[11];
    const float* dWhh1 = (const float*)d_in[12];
    const float* db1   = (const float*)d_in[13];
    const float* fcW   = (const float*)d_in[14];
    const float* fcb   = (const float*)d_in[15];
    float* out = (float*)d_out;

    init_state_kernel<<<(BB * HH + 255) / 256, 256>>>();

    dim3 grid(16, 8);
    lstm_persistent_kernel<<<grid, 512>>>(
        x,
        eWih0, eWhh0, eb0, eWih1, eWhh1, eb1,
        dWih0, dWhh0, db0, dWih1, dWhh1, db1,
        fcW, fcb, out);
}

// round 6
// speedup vs baseline: 1.1252x; 1.1252x over previous
#include <cuda_runtime.h>
#include <math.h>
#include <stdint.h>

#define BB  256
#define TT  168
#define INF 64
#define HH  512
#define HOR 24

// ---- device scratch (no allocations allowed) ----
__device__ float g_h[2][2][BB * HH];     // [layer][pingpong][B*H]
__device__ float g_c[2][BB * HH];        // [layer][B*H]
__device__ float g_fcpart[2][16][BB];    // [pingpong][col-tile][batch]

__device__ __forceinline__ float sigmoidf_(float x) { return 1.0f / (1.0f + expf(-x)); }

__global__ void init_state_kernel() {
    int i = blockIdx.x * blockDim.x + threadIdx.x;
    if (i < BB * HH) {
        g_h[0][0][i] = 0.0f;
        g_h[1][0][i] = 0.0f;
        g_c[0][i]    = 0.0f;
        g_c[1][i]    = 0.0f;
    }
}

// ---------------------------------------------------------------------------
// GEMM tile machinery: cp.async double-buffered.
// BM=32 batch rows x 32 hidden cols x 4 gates, 512 threads, 2x1 micro-tile.
// ---------------------------------------------------------------------------
#define ROWPAD 36
#define A_WORDS (32 * ROWPAD)
#define W_WORDS (128 * ROWPAD)
#define BUF_WORDS (A_WORDS + W_WORDS)

__device__ __forceinline__ void cpasync16(uint32_t s, const void* g) {
    asm volatile("cp.async.cg.shared.global [%0], [%1], 16;\n" :: "r"(s), "l"(g));
}
__device__ __forceinline__ void cpasync_commit() {
    asm volatile("cp.async.commit_group;\n");
}
__device__ __forceinline__ void cpasync_wait0() {
    asm volatile("cp.async.wait_group 0;\n");
}

__device__ __forceinline__ void load_tile(
    uint32_t sbase,
    const float* __restrict__ Ap, int astr, int aoff,
    const float* __restrict__ Wp, int wstr, int woff,
    int bm, int bn, int tid)
{
#pragma unroll
    for (int it = 0; it < 3; it++) {
        if (it == 2 && tid >= 256) break;
        int c = tid + it * 512;
        if (c < 1024) {
            int r  = c >> 3;        // 0..127 : g*32 + n
            int k4 = c & 7;
            int g  = r >> 5;
            int n  = r & 31;
            const float* gp = Wp + (size_t)(g * HH + bn * 32 + n) * wstr + woff + k4 * 4;
            cpasync16(sbase + (uint32_t)(A_WORDS + r * ROWPAD + k4 * 4) * 4u, gp);
        } else {
            int c2 = c - 1024;
            int m  = c2 >> 3;
            int k4 = c2 & 7;
            const float* gp = Ap + (size_t)(bm * 32 + m) * astr + aoff + k4 * 4;
            cpasync16(sbase + (uint32_t)(m * ROWPAD + k4 * 4) * 4u, gp);
        }
    }
}

// Core gate GEMM: acc[g][r] = bias + [Xin | h_prev] @ [Wih | Whh]^T tile.
__device__ __forceinline__ void gemm_gates(
    float acc[4][2],
    const float* __restrict__ Xin, int Kx, int xstride,
    const float* __restrict__ Wih,
    const float* __restrict__ Whh,
    const float* __restrict__ bias,
    const float* __restrict__ h_prev,
    float* smem, uint32_t smem_u32,
    int bn, int bm, int tid, int ty, int col)
{
#pragma unroll
    for (int g = 0; g < 4; g++) {
        float b = bias[g * HH + col];
        acc[g][0] = b;
        acc[g][1] = b;
    }

    const int ntiles = (Kx + HH) >> 5;

    auto resolve = [&](int tile, const float*& Ap, int& astr, int& aoff,
                       const float*& Wp, int& wstr, int& woff) {
        int kt = tile * 32;
        if (kt < Kx) {
            Ap = Xin; astr = xstride; aoff = kt;
            Wp = Wih; wstr = Kx;      woff = kt;
        } else {
            Ap = h_prev; astr = HH; aoff = kt - Kx;
            Wp = Whh;    wstr = HH; woff = kt - Kx;
        }
    };

    {
        const float *Ap, *Wp; int astr, aoff, wstr, woff;
        resolve(0, Ap, astr, aoff, Wp, wstr, woff);
        load_tile(smem_u32, Ap, astr, aoff, Wp, wstr, woff, bm, bn, tid);
        cpasync_commit();
    }

#pragma unroll 1
    for (int t = 0; t < ntiles; t++) {
        cpasync_wait0();
        __syncthreads();

        if (t + 1 < ntiles) {
            const float *Ap, *Wp; int astr, aoff, wstr, woff;
            resolve(t + 1, Ap, astr, aoff, Wp, wstr, woff);
            load_tile(smem_u32 + (uint32_t)((t + 1) & 1) * BUF_WORDS * 4u,
                      Ap, astr, aoff, Wp, wstr, woff, bm, bn, tid);
        }
        cpasync_commit();

        const float* sb  = smem + (t & 1) * BUF_WORDS;
        const float* Asb = sb + ty * 2 * ROWPAD;
        const float* Wsb = sb + A_WORDS + (tid & 31) * ROWPAD;

#pragma unroll
        for (int kg = 0; kg < 8; kg++) {
            float4 a0 = *(const float4*)(Asb + kg * 4);
            float4 a1 = *(const float4*)(Asb + ROWPAD + kg * 4);
#pragma unroll
            for (int g = 0; g < 4; g++) {
                float4 w = *(const float4*)(Wsb + g * 32 * ROWPAD + kg * 4);
                acc[g][0] += a0.x * w.x;
                acc[g][0] += a0.y * w.y;
                acc[g][0] += a0.z * w.z;
                acc[g][0] += a0.w * w.w;
                acc[g][1] += a1.x * w.x;
                acc[g][1] += a1.y * w.y;
                acc[g][1] += a1.z * w.z;
                acc[g][1] += a1.w * w.w;
            }
        }
    }
}

// Standard LSTM epilogue (global c-state). Returns the two h values.
__device__ __forceinline__ void lstm_epilogue(
    float acc[4][2], float* __restrict__ c_state,
    float* __restrict__ h_out, int idx0, int idx1,
    float& hv0, float& hv1)
{
    {
        float ig = sigmoidf_(acc[0][0]);
        float fg = sigmoidf_(acc[1][0]);
        float gg = tanhf(acc[2][0]);
        float og = sigmoidf_(acc[3][0]);
        float c  = fg * c_state[idx0] + ig * gg;
        c_state[idx0] = c;
        hv0 = og * tanhf(c);
        h_out[idx0] = hv0;
    }
    {
        float ig = sigmoidf_(acc[0][1]);
        float fg = sigmoidf_(acc[1][1]);
        float gg = tanhf(acc[2][1]);
        float og = sigmoidf_(acc[3][1]);
        float c  = fg * c_state[idx1] + ig * gg;
        c_state[idx1] = c;
        hv1 = og * tanhf(c);
        h_out[idx1] = hv1;
    }
}

// ---------------------------------------------------------------------------
// Encoder step kernel: z=0 -> job A (L1(t) or edge), z=1 -> job B (L0(t+1)).
// grid (16, 8, 1 or 2). The two jobs are independent; both read h0[t] which
// was written by the previous launch.
// ---------------------------------------------------------------------------
__global__ __launch_bounds__(512, 2) void enc_step_kernel(
    // job A
    const float* __restrict__ A_Xin, int A_K, int A_xstr,
    const float* __restrict__ A_Wih, const float* __restrict__ A_Whh,
    const float* __restrict__ A_b,
    const float* __restrict__ A_hp, float* __restrict__ A_ho,
    float* __restrict__ A_c,
    // job B
    const float* __restrict__ B_Xin, int B_K, int B_xstr,
    const float* __restrict__ B_Wih, const float* __restrict__ B_Whh,
    const float* __restrict__ B_b,
    const float* __restrict__ B_hp, float* __restrict__ B_ho,
    float* __restrict__ B_c)
{
    __shared__ __align__(16) float smem[2 * BUF_WORDS];

    const int tid = threadIdx.x;
    const int ty  = tid >> 5;
    const int bn  = blockIdx.x;
    const int bm  = blockIdx.y;
    const int row0 = bm * 32 + ty * 2;
    const int col  = bn * 32 + (tid & 31);
    const int idx0 = row0 * HH + col;
    const int idx1 = idx0 + HH;

    uint32_t smem_u32;
    {
        void* p = (void*)smem;
        asm("{ .reg .u64 t; cvta.to.shared.u64 t, %1; cvt.u32.u64 %0, t; }"
            : "=r"(smem_u32) : "l"(p));
    }

    const float *Xin, *Wih, *Whh, *bias, *hp;
    float *ho, *cst;
    int Kx, xstr;
    if (blockIdx.z == 0) {
        Xin = A_Xin; Kx = A_K; xstr = A_xstr;
        Wih = A_Wih; Whh = A_Whh; bias = A_b;
        hp = A_hp; ho = A_ho; cst = A_c;
    } else {
        Xin = B_Xin; Kx = B_K; xstr = B_xstr;
        Wih = B_Wih; Whh = B_Whh; bias = B_b;
        hp = B_hp; ho = B_ho; cst = B_c;
    }

    float acc[4][2];
    gemm_gates(acc, Xin, Kx, xstr, Wih, Whh, bias, hp,
               smem, smem_u32, bn, bm, tid, ty, col);
    float hv0, hv1;
    lstm_epilogue(acc, cst, ho, idx0, idx1, hv0, hv1);
}

// ---------------------------------------------------------------------------
// Decoder layer-0 kernel: scalar input = fcb + sum of fc partials from the
// previous step's L1 (or 0 for the first step). Also writes out[:, out_s].
// ---------------------------------------------------------------------------
__global__ __launch_bounds__(512) void dec_l0_kernel(
    const float* __restrict__ part,          // [16][BB] or null (s=0)
    const float* __restrict__ Wscal,         // [2048] (dWih0)
    const float* __restrict__ Whh,
    const float* __restrict__ bias,
    const float* __restrict__ h_prev,
    float* __restrict__ h_out,
    float* __restrict__ c_state,
    const float* __restrict__ fcb,
    float* __restrict__ out, int out_s)
{
    __shared__ __align__(16) float smem[2 * BUF_WORDS];

    const int tid = threadIdx.x;
    const int ty  = tid >> 5;
    const int bn  = blockIdx.x;
    const int bm  = blockIdx.y;
    const int row0 = bm * 32 + ty * 2;
    const int col  = bn * 32 + (tid & 31);
    const int idx0 = row0 * HH + col;
    const int idx1 = idx0 + HH;

    uint32_t smem_u32;
    {
        void* p = (void*)smem;
        asm("{ .reg .u64 t; cvta.to.shared.u64 t, %1; cvt.u32.u64 %0, t; }"
            : "=r"(smem_u32) : "l"(p));
    }

    // fc output from previous step = this step's scalar input (start early
    // so the loads overlap the GEMM prologue)
    float x0 = 0.0f, x1 = 0.0f;
    if (part) {
        float s0 = fcb[0], s1 = fcb[0];
#pragma unroll
        for (int j = 0; j < 16; j++) {
            s0 += part[j * BB + row0];
            s1 += part[j * BB + row0 + 1];
        }
        x0 = s0; x1 = s1;
    }

    float acc[4][2];
    gemm_gates(acc, nullptr, 0, 0, nullptr, Whh, bias, h_prev,
               smem, smem_u32, bn, bm, tid, ty, col);

#pragma unroll
    for (int g = 0; g < 4; g++) {
        float w = Wscal[g * HH + col];
        acc[g][0] += x0 * w;
        acc[g][1] += x1 * w;
    }

    float hv0, hv1;
    lstm_epilogue(acc, c_state, h_out, idx0, idx1, hv0, hv1);

    if (out_s >= 0 && bn == 0 && (tid & 31) == 0) {
        out[row0 * HOR + out_s]       = x0;
        out[(row0 + 1) * HOR + out_s] = x1;
    }
}

// ---------------------------------------------------------------------------
// Decoder layer-1 kernel: full GEMM + fc partials (deterministic, no atomics).
// ---------------------------------------------------------------------------
__global__ __launch_bounds__(512) void dec_l1_kernel(
    const float* __restrict__ Xin,            // h0 new
    const float* __restrict__ Wih,
    const float* __restrict__ Whh,
    const float* __restrict__ bias,
    const float* __restrict__ h_prev,
    float* __restrict__ h_out,
    float* __restrict__ c_state,
    const float* __restrict__ fcW,
    float* __restrict__ partout)              // [16][BB]
{
    __shared__ __align__(16) float smem[2 * BUF_WORDS];

    const int tid = threadIdx.x;
    const int ty  = tid >> 5;
    const int bn  = blockIdx.x;
    const int bm  = blockIdx.y;
    const int row0 = bm * 32 + ty * 2;
    const int col  = bn * 32 + (tid & 31);
    const int idx0 = row0 * HH + col;
    const int idx1 = idx0 + HH;

    uint32_t smem_u32;
    {
        void* p = (void*)smem;
        asm("{ .reg .u64 t; cvta.to.shared.u64 t, %1; cvt.u32.u64 %0, t; }"
            : "=r"(smem_u32) : "l"(p));
    }

    float acc[4][2];
    gemm_gates(acc, Xin, HH, HH, Wih, Whh, bias, h_prev,
               smem, smem_u32, bn, bm, tid, ty, col);
    float hv0, hv1;
    lstm_epilogue(acc, c_state, h_out, idx0, idx1, hv0, hv1);

    // fc partial for this 32-col tile (warp reduce over columns)
    float w = fcW[col];
    float p0 = hv0 * w;
    float p1 = hv1 * w;
#pragma unroll
    for (int o = 16; o; o >>= 1) {
        p0 += __shfl_xor_sync(0xffffffffu, p0, o);
        p1 += __shfl_xor_sync(0xffffffffu, p1, o);
    }
    if ((tid & 31) == 0) {
        partout[bn * BB + row0]     = p0;
        partout[bn * BB + row0 + 1] = p1;
    }
}

// final horizon step output
__global__ void fc_flush_kernel(const float* __restrict__ part,
                                const float* __restrict__ fcb,
                                float* __restrict__ out)
{
    int b = threadIdx.x;
    float s = fcb[0];
#pragma unroll
    for (int j = 0; j < 16; j++) s += part[j * BB + b];
    out[b * HOR + (HOR - 1)] = s;
}

extern "C" void kernel_launch(void* const* d_in, const int* in_sizes, int n_in,
                              void* d_out, int out_size)
{
    const float* x     = (const float*)d_in[0];
    // d_in[1] = y : unused by the reference
    const float* eWih0 = (const float*)d_in[2];
    const float* eWhh0 = (const float*)d_in[3];
    const float* eb0   = (const float*)d_in[4];
    const float* eWih1 = (const float*)d_in[5];
    const float* eWhh1 = (const float*)d_in[6];
    const float* eb1   = (const float*)d_in[7];
    const float* dWih0 = (const float*)d_in[8];   // [2048,1]
    const float* dWhh0 = (const float*)d_in[9];
    const float* db0   = (const float*)d_in[10];
    const float* dWih1 = (const float*)d_in[11];
    const float* dWhh1 = (const float*)d_in[12];
    const float* db1   = (const float*)d_in[13];
    const float* fcW   = (const float*)d_in[14];
    const float* fcb   = (const float*)d_in[15];
    float* out = (float*)d_out;

    void* p;
    cudaGetSymbolAddress(&p, g_h);
    float* hbase = (float*)p;
    float* h0[2] = { hbase,               hbase + BB * HH };
    float* h1[2] = { hbase + 2 * BB * HH, hbase + 3 * BB * HH };
    cudaGetSymbolAddress(&p, g_c);
    float* c0 = (float*)p;
    float* c1 = c0 + BB * HH;
    cudaGetSymbolAddress(&p, g_fcpart);
    float* fcpart[2] = { (float*)p, (float*)p + 16 * BB };

    init_state_kernel<<<(BB * HH + 255) / 256, 256>>>();

    dim3 grid1(16, 8, 1);
    dim3 grid2(16, 8, 2);
    int cur = 0;

    // ---- encoder prologue: L0(0) ----
    enc_step_kernel<<<grid1, 512>>>(
        x, INF, TT * INF, eWih0, eWhh0, eb0, h0[0], h0[1], c0,
        nullptr, 0, 0, nullptr, nullptr, nullptr, nullptr, nullptr, nullptr);

    // ---- encoder main: combined L1(t) + L0(t+1), t = 0..166 ----
    for (int t = 0; t < TT - 1; t++) {
        enc_step_kernel<<<grid2, 512>>>(
            // job A = L1(t): reads h0[t] (= h0[cur^1]) and h1[cur]
            h0[cur ^ 1], HH, HH, eWih1, eWhh1, eb1, h1[cur], h1[cur ^ 1], c1,
            // job B = L0(t+1): reads x(t+1) and h0[t]; writes the buffer
            // h0[cur] (its old contents, h0[t-1], are dead)
            x + (t + 1) * INF, INF, TT * INF, eWih0, eWhh0, eb0,
            h0[cur ^ 1], h0[cur], c0);
        cur ^= 1;
    }

    // ---- encoder epilogue: L1(167) ----
    enc_step_kernel<<<grid1, 512>>>(
        h0[cur ^ 1], HH, HH, eWih1, eWhh1, eb1, h1[cur], h1[cur ^ 1], c1,
        nullptr, 0, 0, nullptr, nullptr, nullptr, nullptr, nullptr, nullptr);
    cur ^= 1;
    // invariant here: latest h0 in h0[cur], latest h1 in h1[cur]

    // ---- decoder: 24 steps, fc folded into the chain ----
    for (int s = 0; s < HOR; s++) {
        dec_l0_kernel<<<grid1, 512>>>(
            (s == 0) ? nullptr : fcpart[(s - 1) & 1],
            dWih0, dWhh0, db0, h0[cur], h0[cur ^ 1], c0,
            fcb, out, s - 1);
        dec_l1_kernel<<<grid1, 512>>>(
            h0[cur ^ 1], dWih1, dWhh1, db1, h1[cur], h1[cur ^ 1], c1,
            fcW, fcpart[s & 1]);
        cur ^= 1;
    }
    fc_flush_kernel<<<1, BB>>>(fcpart[(HOR - 1) & 1], fcb, out);
}

// round 8
// speedup vs baseline: 3.0852x; 2.7419x over previous
#include <cuda_runtime.h>
#include <cuda_bf16.h>
#include <math.h>
#include <stdint.h>

#define BB  256
#define TT  168
#define INF 64
#define HH  512
#define HOR 24
#define NHID 32          // hidden tiles: 512 / 16

// ---------------- device scratch (no allocations allowed) ----------------
__device__ __nv_bfloat16 g_xhi[BB * TT * INF], g_xlo[BB * TT * INF];
__device__ __nv_bfloat16 g_hhi[2][2][BB * HH], g_hlo[2][2][BB * HH];
__device__ float g_c[2][BB * HH];
__device__ float g_part[2][NHID][BB];

__device__ __nv_bfloat16 g_eWih0_hi[2048 * INF], g_eWih0_lo[2048 * INF];
__device__ __nv_bfloat16 g_eWhh0_hi[2048 * HH],  g_eWhh0_lo[2048 * HH];
__device__ __nv_bfloat16 g_eWih1_hi[2048 * HH],  g_eWih1_lo[2048 * HH];
__device__ __nv_bfloat16 g_eWhh1_hi[2048 * HH],  g_eWhh1_lo[2048 * HH];
__device__ __nv_bfloat16 g_dWhh0_hi[2048 * HH],  g_dWhh0_lo[2048 * HH];
__device__ __nv_bfloat16 g_dWih1_hi[2048 * HH],  g_dWih1_lo[2048 * HH];
__device__ __nv_bfloat16 g_dWhh1_hi[2048 * HH],  g_dWhh1_lo[2048 * HH];

__device__ __forceinline__ float sigmoidf_(float x) { return 1.0f / (1.0f + expf(-x)); }

// ---------------- init kernels ----------------
__global__ void conv_split_kernel(const float* __restrict__ s,
                                  __nv_bfloat16* __restrict__ hi,
                                  __nv_bfloat16* __restrict__ lo, int n) {
    for (int i = blockIdx.x * blockDim.x + threadIdx.x; i < n;
         i += gridDim.x * blockDim.x) {
        float v = s[i];
        __nv_bfloat16 h = __float2bfloat16(v);
        hi[i] = h;
        lo[i] = __float2bfloat16(v - __bfloat162float(h));
    }
}

__global__ void zero_state_kernel() {
    int i = blockIdx.x * blockDim.x + threadIdx.x;
    __nv_bfloat16 z = __float2bfloat16(0.0f);
    if (i < 2 * 2 * BB * HH) {
        (&g_hhi[0][0][0])[i] = z;
        (&g_hlo[0][0][0])[i] = z;
    }
    if (i < 2 * BB * HH) (&g_c[0][0])[i] = 0.0f;
}

// ---------------- PTX helpers ----------------
__device__ __forceinline__ uint32_t smem_u32(const void* p) {
    uint32_t a;
    asm("{ .reg .u64 t; cvta.to.shared.u64 t, %1; cvt.u32.u64 %0, t; }"
        : "=r"(a) : "l"(p));
    return a;
}
__device__ __forceinline__ void cpasync16(uint32_t s, const void* g) {
    asm volatile("cp.async.cg.shared.global [%0], [%1], 16;\n" :: "r"(s), "l"(g));
}
__device__ __forceinline__ void cpasync_commit() {
    asm volatile("cp.async.commit_group;\n");
}
__device__ __forceinline__ void cpasync_wait1() {
    asm volatile("cp.async.wait_group 1;\n");
}
__device__ __forceinline__ void cpasync_wait0() {
    asm volatile("cp.async.wait_group 0;\n");
}

__device__ __forceinline__ void ldm_x4(uint32_t addr, uint32_t r[4]) {
    asm volatile("ldmatrix.sync.aligned.m8n8.x4.shared.b16 {%0,%1,%2,%3}, [%4];"
                 : "=r"(r[0]), "=r"(r[1]), "=r"(r[2]), "=r"(r[3]) : "r"(addr));
}
__device__ __forceinline__ void ldm_x2(uint32_t addr, uint32_t r[2]) {
    asm volatile("ldmatrix.sync.aligned.m8n8.x2.shared.b16 {%0,%1}, [%2];"
                 : "=r"(r[0]), "=r"(r[1]) : "r"(addr));
}
__device__ __forceinline__ void mma_bf16(float d[4], const uint32_t a[4],
                                         const uint32_t b[2]) {
    asm volatile("mma.sync.aligned.m16n8k16.row.col.f32.bf16.bf16.f32 "
                 "{%0,%1,%2,%3}, {%4,%5,%6,%7}, {%8,%9}, {%0,%1,%2,%3};"
                 : "+f"(d[0]), "+f"(d[1]), "+f"(d[2]), "+f"(d[3])
                 : "r"(a[0]), "r"(a[1]), "r"(a[2]), "r"(a[3]),
                   "r"(b[0]), "r"(b[1]));
}

#define SWZ(o) ((o) ^ (((o) >> 3) & 0x70))

// smem buffer layout (bytes from dynamic base): A hi/lo 128x64 bf16, W hi/lo 64x64 bf16
#define AHI_OFF 0
#define ALO_OFF 16384
#define WHI_OFF 32768
#define WLO_OFF 40960
#define BUF_BYTES 49152
#define DYN_SMEM (2 * BUF_BYTES)
#define GPAD 80            // epilogue gate-smem row pad (fp32 words)

// ---------------- job descriptor ----------------
struct JobP {
    const __nv_bfloat16 *Ahi, *Alo;       // input segment [*, Kx], row stride astr
    int Kx, astr;
    const __nv_bfloat16 *WihHi, *WihLo;   // [2048, Kx]
    const __nv_bfloat16 *WhhHi, *WhhLo;   // [2048, 512]
    const __nv_bfloat16 *Hhi, *Hlo;       // h_prev [B, 512]
    const float* bias;                    // [2048]
    float* c_state;                       // [B*512]
    __nv_bfloat16 *HoutHi, *HoutLo;       // [B*512]
    int mode;                             // 0 plain, 1 dec0, 2 dec1
    const float* partin;                  // dec0 (null for s==0)
    const float* Wscal;                   // dec0: dWih0 fp32 [2048]
    const float* fcb;                     // dec0
    float* outp; int out_s;               // dec0
    const float* fcW;                     // dec1
    float* partout;                       // dec1: [NHID][BB]
};

// ---------------- fused LSTM step via mma.sync ----------------
// 256 threads (8 warps), tile M=128 x N=64 (4 gates x 16 cols, g-major rows).
// grid (NHID, 2, njobs). Warp tile 32x32: 4 warps in M x 2 in N.
__global__ __launch_bounds__(256) void lstm_mma_kernel(JobP ja, JobP jb)
{
    extern __shared__ char dsmem[];
    __shared__ float xs[128];

    const JobP J = (blockIdx.z == 0) ? ja : jb;
    const int tid  = threadIdx.x;
    const int wid  = tid >> 5;
    const int lane = tid & 31;
    const int hn   = blockIdx.x;
    const int bm   = blockIdx.y;

    const uint32_t sb = smem_u32(dsmem);

    const int wm = (wid & 3) * 32;     // warp M offset within 128
    const int wn = (wid >> 2) * 32;    // warp N offset within 64

    // per-lane ldmatrix address components
    const int a_row_l = (lane & 7) + 8 * ((lane >> 3) & 1);  // row within m16 tile
    const int a_kb_l  = (lane >> 4) * 16;                    // k-byte lane part
    const int b_row_l = lane & 7;                            // row within n8 tile
    const int b_kb_l  = ((lane >> 3) & 1) * 16;

    const int nchunks = (J.Kx + HH) >> 6;

    auto load_chunk = [&](int c, uint32_t sbuf) {
        int k0 = c << 6;
        const __nv_bfloat16 *ah, *al, *wh, *wl;
        int astr, wstr, ao, wo;
        if (k0 < J.Kx) {
            ah = J.Ahi; al = J.Alo; astr = J.astr; ao = k0;
            wh = J.WihHi; wl = J.WihLo; wstr = J.Kx; wo = k0;
        } else {
            ah = J.Hhi; al = J.Hlo; astr = HH; ao = k0 - J.Kx;
            wh = J.WhhHi; wl = J.WhhLo; wstr = HH; wo = k0 - J.Kx;
        }
#pragma unroll
        for (int it = 0; it < 12; it++) {
            int cc = tid + it * 256;
            if (cc < 1024) {            // W: 2 parts x 64 rows x 8 x 16B
                int p   = cc >> 9;
                int r   = (cc >> 3) & 63;
                int k16 = cc & 7;
                int gate = r >> 4, j = r & 15;
                const __nv_bfloat16* src = (p ? wl : wh) +
                    (size_t)(gate * HH + hn * 16 + j) * wstr + wo + k16 * 8;
                cpasync16(sbuf + (p ? WLO_OFF : WHI_OFF) + SWZ(r * 128 + k16 * 16), src);
            } else {                    // A: 2 parts x 128 rows x 8 x 16B
                int aa  = cc - 1024;
                int p   = aa >> 10;
                int r   = (aa >> 3) & 127;
                int k16 = aa & 7;
                const __nv_bfloat16* src = (p ? al : ah) +
                    (size_t)(bm * 128 + r) * astr + ao + k16 * 8;
                cpasync16(sbuf + (p ? ALO_OFF : AHI_OFF) + SWZ(r * 128 + k16 * 16), src);
            }
        }
    };

    float acc[2][4][4];
#pragma unroll
    for (int m = 0; m < 2; m++)
#pragma unroll
        for (int n = 0; n < 4; n++)
#pragma unroll
            for (int e = 0; e < 4; e++) acc[m][n][e] = 0.0f;

    load_chunk(0, sb);
    cpasync_commit();

#pragma unroll 1
    for (int i = 0; i < nchunks; i++) {
        uint32_t buf = sb + (uint32_t)(i & 1) * BUF_BYTES;
        if (i + 1 < nchunks) {
            load_chunk(i + 1, sb + (uint32_t)((i + 1) & 1) * BUF_BYTES);
            cpasync_commit();
            cpasync_wait1();
        } else {
            cpasync_commit();
            cpasync_wait0();
        }
        __syncthreads();

        // precompute per-lane row bases for this buffer
        uint32_t aRow[2], bRow[4];
#pragma unroll
        for (int m = 0; m < 2; m++) {
            int row = wm + m * 16 + a_row_l;
            aRow[m] = buf + row * 128 + (((row & 7) << 4) ^ a_kb_l);
        }
#pragma unroll
        for (int n = 0; n < 4; n++) {
            int row = wn + n * 8 + b_row_l;
            bRow[n] = buf + row * 128 + (((row & 7) << 4) ^ b_kb_l);
        }

#pragma unroll
        for (int ks = 0; ks < 4; ks++) {
            uint32_t kx = (uint32_t)(ks * 32);   // XORs into bits [6:4]
            uint32_t ah[2][4], al[2][4], wh[4][2], wl[4][2];
#pragma unroll
            for (int m = 0; m < 2; m++) {
                ldm_x4((aRow[m] ^ kx) + AHI_OFF, ah[m]);
                ldm_x4((aRow[m] ^ kx) + ALO_OFF, al[m]);
            }
#pragma unroll
            for (int n = 0; n < 4; n++) {
                ldm_x2((bRow[n] ^ kx) + WHI_OFF, wh[n]);
                ldm_x2((bRow[n] ^ kx) + WLO_OFF, wl[n]);
            }
#pragma unroll
            for (int m = 0; m < 2; m++)
#pragma unroll
                for (int n = 0; n < 4; n++) mma_bf16(acc[m][n], ah[m], wh[n]);
#pragma unroll
            for (int m = 0; m < 2; m++)
#pragma unroll
                for (int n = 0; n < 4; n++) mma_bf16(acc[m][n], al[m], wh[n]);
#pragma unroll
            for (int m = 0; m < 2; m++)
#pragma unroll
                for (int n = 0; n < 4; n++) mma_bf16(acc[m][n], ah[m], wl[n]);
        }
        __syncthreads();   // protect buffer i from next chunk's prefetch overwrite
    }

    // decoder L0 scalar input: previous step's fc output (per batch row)
    if (J.mode == 1 && tid < 128) {
        float s = 0.0f;
        if (J.partin) {
            s = J.fcb[0];
#pragma unroll
            for (int j2 = 0; j2 < NHID; j2++) s += J.partin[j2 * BB + bm * 128 + tid];
            if (J.out_s >= 0 && hn == 0) J.outp[(bm * 128 + tid) * HOR + J.out_s] = s;
        }
        xs[tid] = s;
    }

    __syncthreads();   // all ldmatrix reads done; buffers reusable; xs ready

    // store accumulators to smem gate buffer [128][GPAD]
    float* gsm = (float*)dsmem;
    {
        int g = lane >> 2, t = lane & 3;
#pragma unroll
        for (int m = 0; m < 2; m++)
#pragma unroll
            for (int n = 0; n < 4; n++) {
                int r0 = wm + m * 16 + g;
                int cc = wn + n * 8 + 2 * t;
                *(float2*)&gsm[r0 * GPAD + cc]       = make_float2(acc[m][n][0], acc[m][n][1]);
                *(float2*)&gsm[(r0 + 8) * GPAD + cc] = make_float2(acc[m][n][2], acc[m][n][3]);
            }
    }
    __syncthreads();

    // fused epilogue: 128 rows x 16 cols, 8 elements/thread (same j per thread)
    const int j   = tid & 15;
    const int col = hn * 16 + j;
    const float bi = J.bias[col];
    const float bf = J.bias[HH + col];
    const float bg = J.bias[2 * HH + col];
    const float bo = J.bias[3 * HH + col];
    float wsi = 0, wsf = 0, wsg = 0, wso = 0;
    if (J.mode == 1) {
        wsi = J.Wscal[col]; wsf = J.Wscal[HH + col];
        wsg = J.Wscal[2 * HH + col]; wso = J.Wscal[3 * HH + col];
    }
    const float fw = (J.mode == 2) ? J.fcW[col] : 0.0f;

#pragma unroll
    for (int i = 0; i < 8; i++) {
        int r = (tid >> 4) + i * 16;           // local row 0..127
        float pi = gsm[r * GPAD + j]      + bi;
        float pf = gsm[r * GPAD + 16 + j] + bf;
        float pg = gsm[r * GPAD + 32 + j] + bg;
        float po = gsm[r * GPAD + 48 + j] + bo;
        if (J.mode == 1) {
            float xsc = xs[r];
            pi += xsc * wsi; pf += xsc * wsf; pg += xsc * wsg; po += xsc * wso;
        }
        int idx = (bm * 128 + r) * HH + col;
        float c = sigmoidf_(pf) * J.c_state[idx] + sigmoidf_(pi) * tanhf(pg);
        J.c_state[idx] = c;
        float h = sigmoidf_(po) * tanhf(c);
        __nv_bfloat16 hh = __float2bfloat16(h);
        J.HoutHi[idx] = hh;
        J.HoutLo[idx] = __float2bfloat16(h - __bfloat162float(hh));
        if (J.mode == 2) {
            float p = h * fw;                  // reduce over j (4 xor bits)
#pragma unroll
            for (int o = 1; o < 16; o <<= 1) p += __shfl_xor_sync(0xffffffffu, p, o);
            if (j == 0) J.partout[hn * BB + bm * 128 + r] = p;
        }
    }
}

// last horizon column
__global__ void fc_flush_kernel(const float* __restrict__ part,
                                const float* __restrict__ fcb,
                                float* __restrict__ out) {
    int b = threadIdx.x;
    float s = fcb[0];
#pragma unroll
    for (int j = 0; j < NHID; j++) s += part[j * BB + b];
    out[b * HOR + (HOR - 1)] = s;
}

// ---------------- host ----------------
static void* sym(const void* s) { void* p = nullptr; cudaGetSymbolAddress(&p, s); return p; }

extern "C" void kernel_launch(void* const* d_in, const int* in_sizes, int n_in,
                              void* d_out, int out_size)
{
    const float* x     = (const float*)d_in[0];
    const float* eWih0 = (const float*)d_in[2];
    const float* eWhh0 = (const float*)d_in[3];
    const float* eb0   = (const float*)d_in[4];
    const float* eWih1 = (const float*)d_in[5];
    const float* eWhh1 = (const float*)d_in[6];
    const float* eb1   = (const float*)d_in[7];
    const float* dWih0 = (const float*)d_in[8];
    const float* dWhh0 = (const float*)d_in[9];
    const float* db0   = (const float*)d_in[10];
    const float* dWih1 = (const float*)d_in[11];
    const float* dWhh1 = (const float*)d_in[12];
    const float* db1   = (const float*)d_in[13];
    const float* fcW   = (const float*)d_in[14];
    const float* fcb   = (const float*)d_in[15];
    float* out = (float*)d_out;

    cudaFuncSetAttribute(lstm_mma_kernel,
                         cudaFuncAttributeMaxDynamicSharedMemorySize, DYN_SMEM);

    __nv_bfloat16* xhi = (__nv_bfloat16*)sym(g_xhi);
    __nv_bfloat16* xlo = (__nv_bfloat16*)sym(g_xlo);
    __nv_bfloat16* hhi = (__nv_bfloat16*)sym(g_hhi);
    __nv_bfloat16* hlo = (__nv_bfloat16*)sym(g_hlo);
    float* cst  = (float*)sym(g_c);
    float* part = (float*)sym(g_part);

    __nv_bfloat16* eWih0h = (__nv_bfloat16*)sym(g_eWih0_hi);
    __nv_bfloat16* eWih0l = (__nv_bfloat16*)sym(g_eWih0_lo);
    __nv_bfloat16* eWhh0h = (__nv_bfloat16*)sym(g_eWhh0_hi);
    __nv_bfloat16* eWhh0l = (__nv_bfloat16*)sym(g_eWhh0_lo);
    __nv_bfloat16* eWih1h = (__nv_bfloat16*)sym(g_eWih1_hi);
    __nv_bfloat16* eWih1l = (__nv_bfloat16*)sym(g_eWih1_lo);
    __nv_bfloat16* eWhh1h = (__nv_bfloat16*)sym(g_eWhh1_hi);
    __nv_bfloat16* eWhh1l = (__nv_bfloat16*)sym(g_eWhh1_lo);
    __nv_bfloat16* dWhh0h = (__nv_bfloat16*)sym(g_dWhh0_hi);
    __nv_bfloat16* dWhh0l = (__nv_bfloat16*)sym(g_dWhh0_lo);
    __nv_bfloat16* dWih1h = (__nv_bfloat16*)sym(g_dWih1_hi);
    __nv_bfloat16* dWih1l = (__nv_bfloat16*)sym(g_dWih1_lo);
    __nv_bfloat16* dWhh1h = (__nv_bfloat16*)sym(g_dWhh1_hi);
    __nv_bfloat16* dWhh1l = (__nv_bfloat16*)sym(g_dWhh1_lo);

    const int HSZ = BB * HH;
    __nv_bfloat16 *h0hi[2] = { hhi,              hhi + HSZ };
    __nv_bfloat16 *h0lo[2] = { hlo,              hlo + HSZ };
    __nv_bfloat16 *h1hi[2] = { hhi + 2 * HSZ,    hhi + 3 * HSZ };
    __nv_bfloat16 *h1lo[2] = { hlo + 2 * HSZ,    hlo + 3 * HSZ };
    float* c0 = cst;
    float* c1 = cst + HSZ;
    float* pp[2] = { part, part + NHID * BB };

    // ---- init: zero state, convert weights + x to bf16 hi/lo ----
    zero_state_kernel<<<(2 * 2 * BB * HH + 255) / 256, 256>>>();
    conv_split_kernel<<<256, 256>>>(x,     xhi,    xlo,    BB * TT * INF);
    conv_split_kernel<<<256, 256>>>(eWih0, eWih0h, eWih0l, 2048 * INF);
    conv_split_kernel<<<256, 256>>>(eWhh0, eWhh0h, eWhh0l, 2048 * HH);
    conv_split_kernel<<<256, 256>>>(eWih1, eWih1h, eWih1l, 2048 * HH);
    conv_split_kernel<<<256, 256>>>(eWhh1, eWhh1h, eWhh1l, 2048 * HH);
    conv_split_kernel<<<256, 256>>>(dWhh0, dWhh0h, dWhh0l, 2048 * HH);
    conv_split_kernel<<<256, 256>>>(dWih1, dWih1h, dWih1l, 2048 * HH);
    conv_split_kernel<<<256, 256>>>(dWhh1, dWhh1h, dWhh1l, 2048 * HH);

    auto mkL0 = [&](int t, int cur) {
        JobP j{};
        j.Ahi = xhi + t * INF; j.Alo = xlo + t * INF; j.Kx = INF; j.astr = TT * INF;
        j.WihHi = eWih0h; j.WihLo = eWih0l;
        j.WhhHi = eWhh0h; j.WhhLo = eWhh0l;
        j.Hhi = h0hi[cur]; j.Hlo = h0lo[cur];
        j.bias = eb0; j.c_state = c0;
        j.HoutHi = h0hi[cur ^ 1]; j.HoutLo = h0lo[cur ^ 1];
        j.mode = 0; j.out_s = -1;
        return j;
    };
    auto mkL1 = [&](int cur) {
        JobP j{};
        j.Ahi = h0hi[cur ^ 1]; j.Alo = h0lo[cur ^ 1]; j.Kx = HH; j.astr = HH;
        j.WihHi = eWih1h; j.WihLo = eWih1l;
        j.WhhHi = eWhh1h; j.WhhLo = eWhh1l;
        j.Hhi = h1hi[cur]; j.Hlo = h1lo[cur];
        j.bias = eb1; j.c_state = c1;
        j.HoutHi = h1hi[cur ^ 1]; j.HoutLo = h1lo[cur ^ 1];
        j.mode = 0; j.out_s = -1;
        return j;
    };

    dim3 g1(NHID, 2, 1), g2(NHID, 2, 2);
    int cur = 0;

    // ---- encoder ----
    {   // prologue: L0(0)
        JobP a = mkL0(0, 0);
        lstm_mma_kernel<<<g1, 256, DYN_SMEM>>>(a, a);
    }
    for (int t = 0; t < TT - 1; t++) {
        JobP a = mkL1(cur);            // L1(t): reads h0[cur^1], h1[cur]
        JobP b = mkL0(t + 1, cur ^ 1); // L0(t+1): reads x(t+1), h0[cur^1]
        b.Hhi = h0hi[cur ^ 1]; b.Hlo = h0lo[cur ^ 1];
        b.HoutHi = h0hi[cur]; b.HoutLo = h0lo[cur];   // h0[t-1] buffer is dead
        lstm_mma_kernel<<<g2, 256, DYN_SMEM>>>(a, b);
        cur ^= 1;
    }
    {   // epilogue: L1(167)
        JobP a = mkL1(cur);
        lstm_mma_kernel<<<g1, 256, DYN_SMEM>>>(a, a);
        cur ^= 1;
    }
    // invariant: latest h0 in h0*[cur], latest h1 in h1*[cur]

    // ---- decoder ----
    for (int s = 0; s < HOR; s++) {
        JobP a{};   // dec L0
        a.Ahi = nullptr; a.Alo = nullptr; a.Kx = 0; a.astr = 0;
        a.WihHi = nullptr; a.WihLo = nullptr;
        a.WhhHi = dWhh0h; a.WhhLo = dWhh0l;
        a.Hhi = h0hi[cur]; a.Hlo = h0lo[cur];
        a.bias = db0; a.c_state = c0;
        a.HoutHi = h0hi[cur ^ 1]; a.HoutLo = h0lo[cur ^ 1];
        a.mode = 1;
        a.partin = (s == 0) ? nullptr : pp[(s - 1) & 1];
        a.Wscal = dWih0; a.fcb = fcb; a.outp = out; a.out_s = s - 1;
        lstm_mma_kernel<<<g1, 256, DYN_SMEM>>>(a, a);

        JobP b{};   // dec L1 (+ fc partials)
        b.Ahi = h0hi[cur ^ 1]; b.Alo = h0lo[cur ^ 1]; b.Kx = HH; b.astr = HH;
        b.WihHi = dWih1h; b.WihLo = dWih1l;
        b.WhhHi = dWhh1h; b.WhhLo = dWhh1l;
        b.Hhi = h1hi[cur]; b.Hlo = h1lo[cur];
        b.bias = db1; b.c_state = c1;
        b.HoutHi = h1hi[cur ^ 1]; b.HoutLo = h1lo[cur ^ 1];
        b.mode = 2; b.out_s = -1;
        b.fcW = fcW; b.partout = pp[s & 1];
        lstm_mma_kernel<<<g1, 256, DYN_SMEM>>>(b, b);
        cur ^= 1;
    }
    fc_flush_kernel<<<1, BB>>>(pp[(HOR - 1) & 1], fcb, out);
}